// round 6
// baseline (speedup 1.0000x reference)
#include <cuda_runtime.h>
#include <math.h>
#include <float.h>

// WaveNet autoregressive generation, sm_103a — round 5: shuffle-reduce rewrite.
// 64 CTAs x 2 rows, 256 threads. All matvecs are register quad-dots with
// warp-shuffle k-reduction (no smem partials), gate fused into the conv phase
// (2 barriers/layer), skip accumulated in registers across all 30 layers.

#define NLAYER 30
#define BB 128
#define VV 256
#define RING_PER_ROW 3069   // 3 * (2^10 - 1) slots, 64 floats each

__device__ float g_ring[(size_t)BB * RING_PER_ROW * 64];  // ~100.6 MB scratch

// Load N float4 weight rows (row stride = stride4 float4s) into registers.
template<int N>
__device__ __forceinline__ void wload(float4* dst, const float4* __restrict__ Wg,
                                      int stride4) {
#pragma unroll
    for (int u = 0; u < N; u++) dst[u] = Wg[(size_t)u * stride4];
}

// FMA N k-steps from a prefetched register weight buffer; acts from smem (f4 chunks).
template<int N>
__device__ __forceinline__ void dotA(const float* __restrict__ as,
                                     const float4* w, float4& o) {
#pragma unroll
    for (int c2 = 0; c2 < N; c2 += 4) {
        float av[4];
        *(float4*)av = *(const float4*)&as[c2];
#pragma unroll
        for (int u = 0; u < 4; u++) {
            float x = av[u];
            const float4 wv = w[c2 + u];
            o.x = fmaf(x, wv.x, o.x);
            o.y = fmaf(x, wv.y, o.y);
            o.z = fmaf(x, wv.z, o.z);
            o.w = fmaf(x, wv.w, o.w);
        }
    }
}

// FMA N k-steps streaming weights straight from global (independent LDGs pipeline).
template<int N>
__device__ __forceinline__ void dotL(const float* __restrict__ as,
                                     const float4* __restrict__ Wg, int stride4,
                                     float4& o) {
#pragma unroll
    for (int c2 = 0; c2 < N; c2 += 4) {
        float av[4];
        *(float4*)av = *(const float4*)&as[c2];
#pragma unroll
        for (int u = 0; u < 4; u++) {
            float4 wv = Wg[(size_t)(c2 + u) * stride4];
            float x = av[u];
            o.x = fmaf(x, wv.x, o.x);
            o.y = fmaf(x, wv.y, o.y);
            o.z = fmaf(x, wv.z, o.z);
            o.w = fmaf(x, wv.w, o.w);
        }
    }
}

__device__ __forceinline__ float4 bfly(float4 o, int m) {
    o.x += __shfl_xor_sync(0xffffffffu, o.x, m);
    o.y += __shfl_xor_sync(0xffffffffu, o.y, m);
    o.z += __shfl_xor_sync(0xffffffffu, o.z, m);
    o.w += __shfl_xor_sync(0xffffffffu, o.w, m);
    return o;
}

// tanh(a) * sigmoid(b), overflow-safe fast-math form.
__device__ __forceinline__ float gate1(float a, float b) {
    float e2 = __expf(2.f * a);
    float t = 1.f - __fdividef(2.f, e2 + 1.f);
    float s = __fdividef(1.f, 1.f + __expf(-b));
    return t * s;
}

__global__ __launch_bounds__(256, 1)
void wavenet_kernel(const int* __restrict__ seed,
                    const float* __restrict__ emb,     // (V, 64)
                    const float* __restrict__ kern,    // (L, 2, 64, 128)
                    const float* __restrict__ cbias,   // (L, 128)
                    const float* __restrict__ rw,      // (L, 64, 64)
                    const float* __restrict__ rb,      // (L, 64)
                    const float* __restrict__ sw,      // (L, 64, 256)
                    const float* __restrict__ sb,      // (L, 256)
                    const float* __restrict__ ow0,     // (256, 256)
                    const float* __restrict__ ob0,     // (256)
                    const float* __restrict__ ow1,     // (256, 256)
                    const float* __restrict__ ob1,     // (256)
                    float* __restrict__ out,
                    int T, long long samp_off, long long logit_off, int mode)
{
    __shared__ __align__(16) float sx[2][64];
    __shared__ __align__(16) float sxl[2][64];
    __shared__ __align__(16) float sg[2][64];
    __shared__ __align__(16) float ssk[2][256];
    __shared__ __align__(16) float sh0[2][256];
    __shared__ __align__(16) float slg[2][256];
    __shared__ __align__(16) float cbs[NLAYER * 128];  // staged conv bias
    __shared__ __align__(16) float rbs[NLAYER * 64];   // staged res bias
    __shared__ __align__(16) float ssb[256];           // sum of skip biases
    __shared__ __align__(16) float obs0[256], obs1[256];
    __shared__ int snidx[2];

    const int tid = threadIdx.x;
    const int row0 = blockIdx.x * 2;

    // conv: dot cd in [0,64) = {r(1) | qq(4) pair-interleaved with half(1)}, 4-way ksplit
    const int cd = tid >> 2, cks = tid & 3;
    const int cr = cd >> 5, cqq = (cd >> 1) & 15, chalf = cd & 1;
    const int cjq = cqq + (chalf ? 16 : 0);      // j-quad in [0,32)
    const int cmat = cks >> 1;                   // 0: x_last@K0, 1: x@K1
    const int ckk = cks & 1;                     // k half within the matrix
    // skip/head: dot sd in [0,128), 2-way ksplit
    const int sd = tid >> 1, sks = tid & 1;
    const int sr = sd >> 6, sq = sd & 63;
    const int sk0 = sks * 32;                    // skip k offset (K=64)
    const int hk0 = sks * 128;                   // head k offset (K=256)
    // res: dot rd in [0,32), 8-way ksplit
    const int rd = tid >> 3, rks = tid & 7;
    const int rr2 = rd >> 4, rq = rd & 15, rk0 = rks * 8;
    // scalar lanes (tid < 128)
    const int r = tid >> 6, c = tid & 63;

    float4 cpre[12], spre[12], rpre[8];
    float4 o_skip;
    float rpop = 0.f;

    // ---- one-time staging ----
    for (int idx = tid; idx < NLAYER * 128; idx += 256) cbs[idx] = cbias[idx];
    for (int idx = tid; idx < NLAYER * 64;  idx += 256) rbs[idx] = rb[idx];
    {
        float s = 0.f;
#pragma unroll 1
        for (int i = 0; i < NLAYER; i++) s += sb[i * 256 + tid];
        ssb[tid] = s;
        obs0[tid] = ob0[tid];
        obs1[tid] = ob1[tid];
    }
    if (tid < 2) snidx[tid] = seed[row0 + tid];
    // prefetch conv layer 0 (t=0); layer-0 pop at t=0 is zero (t < d)
    wload<12>(cpre, (const float4*)kern + ((size_t)cmat * 64 + ckk * 32) * 32 + cjq, 32);
    __syncthreads();

#pragma unroll 1
    for (int t = 0; t < T; t++) {
        // ---- step head ----
        if (tid < 128) {
            sx[r][c] = emb[(size_t)snidx[r] * 64 + c];
            sxl[r][c] = rpop;
        }
        o_skip.x = o_skip.y = o_skip.z = o_skip.w = 0.f;
        __syncthreads();

#pragma unroll 1
        for (int i = 0; i < NLAYER; i++) {
            const int d = 1 << (i % 10);
            const long long off = (long long)(i / 10) * 1023 + (d - 1);

            // ================= Phase A: conv + gate =================
            float4 o = {0.f, 0.f, 0.f, 0.f};
            {
                const float4* Wc = (const float4*)kern
                    + ((size_t)(i * 2 + cmat) * 64 + ckk * 32) * 32 + cjq;
                const float* act = (cmat ? sx[cr] : sxl[cr]) + ckk * 32;
                dotA<12>(act, cpre, o);
                dotL<20>(act + 12, Wc + 12 * 32, 32, o);
            }
            // ring push of this layer's input; prefetch next layer's pop
            if (tid < 128) {
                size_t idx = ((size_t)(row0 + r) * RING_PER_ROW + (size_t)off
                              + (t & (d - 1))) * 64 + c;
                g_ring[idx] = sx[r][c];
                if (i < NLAYER - 1) {
                    const int d2 = 1 << ((i + 1) % 10);
                    const long long off2 = (long long)((i + 1) / 10) * 1023 + (d2 - 1);
                    size_t idx2 = ((size_t)(row0 + r) * RING_PER_ROW + (size_t)off2
                                   + (t & (d2 - 1))) * 64 + c;
                    rpop = (t >= d2) ? g_ring[idx2] : 0.f;
                }
            }
            // prefetch skip + res weights for Phase B
            wload<12>(spre, (const float4*)sw + ((size_t)i * 64 + sk0) * 64 + sq, 64);
            wload<8>(rpre,  (const float4*)rw + ((size_t)i * 64 + rk0) * 16 + rq, 16);
            // k-reduce (4 lanes) then pair tanh-half with sigmoid-half (xor 4)
            o = bfly(o, 1);
            o = bfly(o, 2);
            float4 hs;
            hs.x = __shfl_xor_sync(0xffffffffu, o.x, 4);
            hs.y = __shfl_xor_sync(0xffffffffu, o.y, 4);
            hs.z = __shfl_xor_sync(0xffffffffu, o.z, 4);
            hs.w = __shfl_xor_sync(0xffffffffu, o.w, 4);
            if (chalf == 0 && cks == 0) {
                const float4 cbt = *(const float4*)&cbs[i * 128 + 4 * cqq];
                const float4 cbg = *(const float4*)&cbs[i * 128 + 64 + 4 * cqq];
                float4 g;
                g.x = gate1(o.x + cbt.x, hs.x + cbg.x);
                g.y = gate1(o.y + cbt.y, hs.y + cbg.y);
                g.z = gate1(o.z + cbt.z, hs.z + cbg.z);
                g.w = gate1(o.w + cbt.w, hs.w + cbg.w);
                *(float4*)&sg[cr][4 * cqq] = g;
            }
            __syncthreads();

            // ================= Phase B: skip (reg accum) + res =================
            {
                const float4* Ws = (const float4*)sw
                    + ((size_t)i * 64 + sk0) * 64 + sq;
                const float* act = sg[sr] + sk0;
                dotA<12>(act, spre, o_skip);
                dotL<20>(act + 12, Ws + 12 * 64, 64, o_skip);
            }
            {
                float4 ro = {0.f, 0.f, 0.f, 0.f};
                dotA<8>(sg[rr2] + rk0, rpre, ro);
                ro = bfly(ro, 1);
                ro = bfly(ro, 2);
                ro = bfly(ro, 4);
                if (rks == 0) {
                    float4 xo = *(float4*)&sx[rr2][4 * rq];
                    const float4 rbq = *(const float4*)&rbs[i * 64 + 4 * rq];
                    xo.x += ro.x + rbq.x;
                    xo.y += ro.y + rbq.y;
                    xo.z += ro.z + rbq.z;
                    xo.w += ro.w + rbq.w;
                    *(float4*)&sx[rr2][4 * rq] = xo;
                }
            }
            if (tid < 128 && i < NLAYER - 1) sxl[r][c] = rpop;
            // prefetch next conv (or head W0 for the last layer)
            if (i < NLAYER - 1) {
                wload<12>(cpre, (const float4*)kern
                    + ((size_t)((i + 1) * 2 + cmat) * 64 + ckk * 32) * 32 + cjq, 32);
            } else {
                wload<12>(cpre, (const float4*)ow0 + (size_t)hk0 * 64 + sq, 64);
            }
            __syncthreads();
        }

        // ---- skip finalize: pair-reduce + Σbias + relu ----
        {
            float4 os = bfly(o_skip, 1);
            if (sks == 0) {
                const float4 bq = *(const float4*)&ssb[4 * sq];
                float4 v;
                v.x = fmaxf(os.x + bq.x, 0.f);
                v.y = fmaxf(os.y + bq.y, 0.f);
                v.z = fmaxf(os.z + bq.z, 0.f);
                v.w = fmaxf(os.w + bq.w, 0.f);
                *(float4*)&ssk[sr][4 * sq] = v;
            }
        }
        __syncthreads();

        // ---- head m0: h0 = relu(skip @ ow0 + ob0) ----
        {
            float4 o = {0.f, 0.f, 0.f, 0.f};
            const float* act = ssk[sr] + hk0;
            dotA<12>(act, cpre, o);
            dotL<116>(act + 12, (const float4*)ow0 + (size_t)(hk0 + 12) * 64 + sq, 64, o);
            wload<12>(cpre, (const float4*)ow1 + (size_t)hk0 * 64 + sq, 64);
            o = bfly(o, 1);
            if (sks == 0) {
                const float4 bq = *(const float4*)&obs0[4 * sq];
                float4 v;
                v.x = fmaxf(o.x + bq.x, 0.f);
                v.y = fmaxf(o.y + bq.y, 0.f);
                v.z = fmaxf(o.z + bq.z, 0.f);
                v.w = fmaxf(o.w + bq.w, 0.f);
                *(float4*)&sh0[sr][4 * sq] = v;
            }
        }
        __syncthreads();

        // ---- head m1: logits = h0 @ ow1 + ob1 ----
        {
            float4 o = {0.f, 0.f, 0.f, 0.f};
            const float* act = sh0[sr] + hk0;
            dotA<12>(act, cpre, o);
            dotL<116>(act + 12, (const float4*)ow1 + (size_t)(hk0 + 12) * 64 + sq, 64, o);
            // prefetch (t+1, layer 0) conv weights + layer-0 pop
            wload<12>(cpre, (const float4*)kern
                + ((size_t)cmat * 64 + ckk * 32) * 32 + cjq, 32);
            if (tid < 128)
                rpop = g_ring[((size_t)(row0 + r) * RING_PER_ROW) * 64 + c];
            o = bfly(o, 1);
            if (sks == 0) {
                const float4 bq = *(const float4*)&obs1[4 * sq];
                float4 v;
                v.x = o.x + bq.x;
                v.y = o.y + bq.y;
                v.z = o.z + bq.z;
                v.w = o.w + bq.w;
                *(float4*)&slg[sr][4 * sq] = v;
                if (mode & 2)
                    *(float4*)&out[logit_off + ((size_t)(row0 + sr) * T + t) * VV + 4 * sq] = v;
            }
        }
        __syncthreads();

        // ---- argmax per row (first-max tie rule, matches jnp.argmax) ----
        if (tid < 64) {
            int rr = tid >> 5, lane = tid & 31;
            float bv = -FLT_MAX;
            int bi = 0;
#pragma unroll
            for (int jj = 0; jj < 8; jj++) {
                int j = lane + jj * 32;
                float v = slg[rr][j];
                if (v > bv) { bv = v; bi = j; }
            }
#pragma unroll
            for (int o2 = 16; o2 > 0; o2 >>= 1) {
                float ov = __shfl_down_sync(0xffffffffu, bv, o2);
                int   oi = __shfl_down_sync(0xffffffffu, bi, o2);
                if (ov > bv || (ov == bv && oi < bi)) { bv = ov; bi = oi; }
            }
            if (lane == 0) {
                snidx[rr] = bi;
                if (mode & 1) out[samp_off + (size_t)(row0 + rr) * T + t] = (float)bi;
                if (mode & 4) ((int*)out)[(size_t)(row0 + rr) * T + t] = bi;
            }
        }
        __syncthreads();
    }
}

extern "C" void kernel_launch(void* const* d_in, const int* in_sizes, int n_in,
                              void* d_out, int out_size) {
    const int*   seed  = (const int*)d_in[0];
    const float* emb   = (const float*)d_in[1];
    const float* kern  = (const float*)d_in[2];
    const float* cbias = (const float*)d_in[3];
    const float* rw    = (const float*)d_in[4];
    const float* rb    = (const float*)d_in[5];
    const float* sw    = (const float*)d_in[6];
    const float* sb    = (const float*)d_in[7];
    const float* ow0   = (const float*)d_in[8];
    const float* ob0   = (const float*)d_in[9];
    const float* ow1   = (const float*)d_in[10];
    const float* ob1   = (const float*)d_in[11];
    (void)in_sizes; (void)n_in;

    int T, mode;
    long long samp_off = 0, logit_off = 0;
    if (out_size % (BB * (VV + 1)) == 0) {
        T = out_size / (BB * (VV + 1));
        mode = 1 | 2;                       // float samples then logits
        samp_off = 0;
        logit_off = (long long)BB * T;
    } else if (out_size % (BB * VV) == 0) {
        T = out_size / (BB * VV);
        mode = 2;                           // logits only
        logit_off = 0;
    } else {
        T = out_size / BB;
        mode = 4;                           // int32 samples only
    }

    wavenet_kernel<<<BB / 2, 256>>>(seed, emb, kern, cbias, rw, rb, sw, sb,
                                    ow0, ob0, ow1, ob1,
                                    (float*)d_out, T, samp_off, logit_off, mode);
}

// round 7
// speedup vs baseline: 5.0638x; 5.0638x over previous
#include <cuda_runtime.h>
#include <math.h>
#include <float.h>

// WaveNet autoregressive generation, sm_103a — round 6.
// R3 structure (coalesced weight LDGs: lanes = consecutive j-quads, k-split
// across warps, both rows per thread sharing each weight load) with:
//  - prefetch buffers shrunk 36->20 float4 (no register spill)
//  - biases staged in smem once (no per-layer L2 bias reads)
//  - skip accumulated in registers across all 30 layers (one reduce per step)
//  - explicit tree reductions + fast gate math

#define NLAYER 30
#define BB 128
#define VV 256
#define RING_PER_ROW 3069   // 3 * (2^10 - 1) slots, 64 floats each

__device__ float g_ring[(size_t)BB * RING_PER_ROW * 64];  // ~100.6 MB scratch

template<int N>
__device__ __forceinline__ void wload(float4* dst, const float4* __restrict__ Wg,
                                      int s4) {
#pragma unroll
    for (int u = 0; u < N; u++) dst[u] = Wg[(size_t)u * s4];
}

// FMA N k-steps (N%4==0), both rows, weights from a register buffer.
template<int N>
__device__ __forceinline__ void mm_reg(const float* __restrict__ a0,
                                       const float* __restrict__ a1,
                                       const float4* w, float4& o0, float4& o1) {
#pragma unroll
    for (int c2 = 0; c2 < N; c2 += 4) {
        float v0[4], v1[4];
        *(float4*)v0 = *(const float4*)(a0 + c2);
        *(float4*)v1 = *(const float4*)(a1 + c2);
#pragma unroll
        for (int u = 0; u < 4; u++) {
            const float4 wv = w[c2 + u];
            o0.x = fmaf(v0[u], wv.x, o0.x);
            o0.y = fmaf(v0[u], wv.y, o0.y);
            o0.z = fmaf(v0[u], wv.z, o0.z);
            o0.w = fmaf(v0[u], wv.w, o0.w);
            o1.x = fmaf(v1[u], wv.x, o1.x);
            o1.y = fmaf(v1[u], wv.y, o1.y);
            o1.z = fmaf(v1[u], wv.z, o1.z);
            o1.w = fmaf(v1[u], wv.w, o1.w);
        }
    }
}

// FMA N k-steps streaming weights from global (independent LDGs pipeline).
template<int N>
__device__ __forceinline__ void mm_gl(const float* __restrict__ a0,
                                      const float* __restrict__ a1,
                                      const float4* __restrict__ Wg, int s4,
                                      float4& o0, float4& o1) {
#pragma unroll
    for (int c2 = 0; c2 < N; c2 += 4) {
        float v0[4], v1[4];
        *(float4*)v0 = *(const float4*)(a0 + c2);
        *(float4*)v1 = *(const float4*)(a1 + c2);
#pragma unroll
        for (int u = 0; u < 4; u++) {
            const float4 wv = Wg[(size_t)(c2 + u) * s4];
            o0.x = fmaf(v0[u], wv.x, o0.x);
            o0.y = fmaf(v0[u], wv.y, o0.y);
            o0.z = fmaf(v0[u], wv.z, o0.z);
            o0.w = fmaf(v0[u], wv.w, o0.w);
            o1.x = fmaf(v1[u], wv.x, o1.x);
            o1.y = fmaf(v1[u], wv.y, o1.y);
            o1.z = fmaf(v1[u], wv.z, o1.z);
            o1.w = fmaf(v1[u], wv.w, o1.w);
        }
    }
}

__global__ __launch_bounds__(256, 1)
void wavenet_kernel(const int* __restrict__ seed,
                    const float* __restrict__ emb,     // (V, 64)
                    const float* __restrict__ kern,    // (L, 2, 64, 128)
                    const float* __restrict__ cbias,   // (L, 128)
                    const float* __restrict__ rw,      // (L, 64, 64)
                    const float* __restrict__ rb,      // (L, 64)
                    const float* __restrict__ sw,      // (L, 64, 256)
                    const float* __restrict__ sb,      // (L, 256)
                    const float* __restrict__ ow0,     // (256, 256)
                    const float* __restrict__ ob0,     // (256)
                    const float* __restrict__ ow1,     // (256, 256)
                    const float* __restrict__ ob1,     // (256)
                    float* __restrict__ out,
                    int T, long long samp_off, long long logit_off, int mode)
{
    __shared__ __align__(16) float sx[2][64];
    __shared__ __align__(16) float sxl[2][64];
    __shared__ __align__(16) float sg[2][64];
    __shared__ __align__(16) float ssk[2][256];
    __shared__ __align__(16) float sh0[2][256];
    __shared__ __align__(16) float slg[2][256];
    __shared__ __align__(16) float cbs[NLAYER * 128];   // staged conv bias
    __shared__ __align__(16) float rbs[NLAYER * 64];    // staged res bias
    __shared__ __align__(16) float ssb[256];            // sum of skip biases
    __shared__ __align__(16) float obs0[256], obs1[256];
    __shared__ __align__(16) float pbuf[2048];           // 8KB partials union
    __shared__ int snidx[2];

    float (*scp)[2][128] = (float(*)[2][128])pbuf;   // [8][2][128] conv
    float (*srp)[2][64]  = (float(*)[2][64])pbuf;    // [16][2][64] res
    float (*ssp)[2][256] = (float(*)[2][256])pbuf;   // [4][2][256] skip/head

    const int tid = threadIdx.x;
    const int row0 = blockIdx.x * 2;

    // lanes = consecutive j-quads (coalesced LDG); k-split across warps
    const int jqc = tid & 31, ksc = tid >> 5, kbc = ksc * 8;   // conv 32jq x 8ks
    const int jqr = tid & 15, ksr = tid >> 4, kbr = ksr * 4;   // res  16jq x 16ks
    const int jqs = tid & 63, kss = tid >> 6, kbs = kss * 16;  // skip 64jq x 4ks
    const int jqh = jqs,      ksh = kss,      kbh = kss * 64;  // head 64jq x 4ks
    const int r = tid >> 6, c = tid & 63;                      // tid<128 combines
    const int ch = tid;                                        // head combine col

    float4 wk[8];   // conv K0[0..3]|K1[4..7] prefetch, or head rows
    float4 wr[4];   // res prefetch
    float4 ws[8];   // skip prefetch, or head rows
    float4 oskip0 = {0,0,0,0}, oskip1 = {0,0,0,0};  // skip reg accumulators
    float  rpop = 0.f;

    // ---- one-time staging ----
    for (int idx = tid; idx < NLAYER * 128; idx += 256) cbs[idx] = cbias[idx];
    for (int idx = tid; idx < NLAYER * 64;  idx += 256) rbs[idx] = rb[idx];
    {
        float s = 0.f;
#pragma unroll 1
        for (int i = 0; i < NLAYER; i++) s += sb[i * 256 + tid];
        ssb[tid] = s;
        obs0[tid] = ob0[tid];
        obs1[tid] = ob1[tid];
    }
    if (tid < 2) snidx[tid] = seed[row0 + tid];
    // prefetch conv (t=0, layer 0); layer-0 pop at t=0 is zero
    wload<4>(wk,     (const float4*)kern + (size_t)kbc * 32 + jqc,             32);
    wload<4>(wk + 4, (const float4*)kern + (size_t)(64 + kbc) * 32 + jqc,      32);
    __syncthreads();

#pragma unroll 1
    for (int t = 0; t < T; t++) {
        // ---- step head ----
        if (tid < 128) {
            sx[r][c] = emb[(size_t)snidx[r] * 64 + c];
            sxl[r][c] = rpop;
        }
        oskip0.x = oskip0.y = oskip0.z = oskip0.w = 0.f;
        oskip1.x = oskip1.y = oskip1.z = oskip1.w = 0.f;
        __syncthreads();

#pragma unroll 1
        for (int i = 0; i < NLAYER; i++) {
            const int d = 1 << (i % 10);
            const long long off = (long long)(i / 10) * 1023 + (d - 1);

            // ---- Phase A: conv FMA (4 pre + 4 stream per matrix) + push + wr/ws
            {
                const float4* K0 = (const float4*)kern
                    + (size_t)(i * 2) * 64 * 32 + (size_t)kbc * 32 + jqc;
                const float4* K1 = K0 + 64 * 32;
                float4 o0 = {0,0,0,0}, o1 = {0,0,0,0};
                mm_reg<4>(sxl[0] + kbc,     sxl[1] + kbc,     wk,     o0, o1);
                mm_gl<4> (sxl[0] + kbc + 4, sxl[1] + kbc + 4, K0 + 4 * 32, 32, o0, o1);
                mm_reg<4>(sx[0] + kbc,      sx[1] + kbc,      wk + 4, o0, o1);
                mm_gl<4> (sx[0] + kbc + 4,  sx[1] + kbc + 4,  K1 + 4 * 32, 32, o0, o1);
                *(float4*)&scp[ksc][0][4 * jqc] = o0;
                *(float4*)&scp[ksc][1][4 * jqc] = o1;
            }
            if (tid < 128) {
                size_t idx = ((size_t)(row0 + r) * RING_PER_ROW + (size_t)off
                              + (t & (d - 1))) * 64 + c;
                g_ring[idx] = sx[r][c];
            }
            wload<4>(wr, (const float4*)rw + (size_t)i * 64 * 16
                         + (size_t)kbr * 16 + jqr, 16);
            wload<8>(ws, (const float4*)sw + (size_t)i * 64 * 64
                         + (size_t)kbs * 64 + jqs, 64);
            __syncthreads();

            // ---- Phase B: gate + next conv (or head W0) prefetch + next pop ----
            if (i < NLAYER - 1) {
                const float4* KN = (const float4*)kern + (size_t)((i + 1) * 2) * 64 * 32;
                wload<4>(wk,     KN + (size_t)kbc * 32 + jqc,        32);
                wload<4>(wk + 4, KN + (size_t)(64 + kbc) * 32 + jqc, 32);
                if (tid < 128) {
                    const int d2 = 1 << ((i + 1) % 10);
                    const long long off2 = (long long)((i + 1) / 10) * 1023 + (d2 - 1);
                    size_t idx2 = ((size_t)(row0 + r) * RING_PER_ROW + (size_t)off2
                                   + (t & (d2 - 1))) * 64 + c;
                    rpop = (t >= d2) ? g_ring[idx2] : 0.f;
                }
            } else {
                wload<8>(wk, (const float4*)ow0 + (size_t)kbh * 64 + jqh, 64);
            }
            if (tid < 128) {
                float p0 = scp[0][r][c], p1 = scp[1][r][c];
                float p2 = scp[2][r][c], p3 = scp[3][r][c];
                float p4 = scp[4][r][c], p5 = scp[5][r][c];
                float p6 = scp[6][r][c], p7 = scp[7][r][c];
                float q0 = scp[0][r][c+64], q1 = scp[1][r][c+64];
                float q2 = scp[2][r][c+64], q3 = scp[3][r][c+64];
                float q4 = scp[4][r][c+64], q5 = scp[5][r][c+64];
                float q6 = scp[6][r][c+64], q7 = scp[7][r][c+64];
                float ht = (((p0+p1)+(p2+p3)) + ((p4+p5)+(p6+p7))) + cbs[i*128 + c];
                float hs = (((q0+q1)+(q2+q3)) + ((q4+q5)+(q6+q7))) + cbs[i*128 + 64 + c];
                float e2 = __expf(2.f * ht);
                float th = 1.f - __fdividef(2.f, e2 + 1.f);
                float sig = __fdividef(1.f, 1.f + __expf(-hs));
                sg[r][c] = th * sig;
            }
            __syncthreads();

            // ---- Phase C: res FMA (partials) + skip FMA (register accumulate) --
            {
                float4 o0 = {0,0,0,0}, o1 = {0,0,0,0};
                mm_reg<4>(sg[0] + kbr, sg[1] + kbr, wr, o0, o1);
                *(float4*)&srp[ksr][0][4 * jqr] = o0;
                *(float4*)&srp[ksr][1][4 * jqr] = o1;
            }
            {
                const float4* SW = (const float4*)sw + (size_t)i * 64 * 64
                                   + (size_t)kbs * 64 + jqs;
                mm_reg<8>(sg[0] + kbs,     sg[1] + kbs,     ws, oskip0, oskip1);
                mm_gl<8> (sg[0] + kbs + 8, sg[1] + kbs + 8, SW + 8 * 64, 64,
                          oskip0, oskip1);
            }
            __syncthreads();

            // ---- Phase D: x combine (tree-16) + stage next sxl ----
            if (tid < 128) {
                float a0 = srp[0][r][c] + srp[1][r][c];
                float a1 = srp[2][r][c] + srp[3][r][c];
                float a2 = srp[4][r][c] + srp[5][r][c];
                float a3 = srp[6][r][c] + srp[7][r][c];
                float a4 = srp[8][r][c] + srp[9][r][c];
                float a5 = srp[10][r][c] + srp[11][r][c];
                float a6 = srp[12][r][c] + srp[13][r][c];
                float a7 = srp[14][r][c] + srp[15][r][c];
                float v = sx[r][c] + rbs[i*64 + c]
                        + (((a0+a1)+(a2+a3)) + ((a4+a5)+(a6+a7)));
                sx[r][c] = v;
                if (i < NLAYER - 1) sxl[r][c] = rpop;
            }
            if (i == NLAYER - 1)
                wload<8>(ws, (const float4*)ow0 + (size_t)(kbh + 8) * 64 + jqh, 64);
            __syncthreads();
        }

        // ---- skip finalize: STS register partials ----
        *(float4*)&ssp[kss][0][4 * jqs] = oskip0;
        *(float4*)&ssp[kss][1][4 * jqs] = oskip1;
        __syncthreads();
        // combine + Σbias + relu (256 threads x 2 rows)
        {
            float v0 = ssb[ch] + ((ssp[0][0][ch] + ssp[1][0][ch])
                                + (ssp[2][0][ch] + ssp[3][0][ch]));
            float v1 = ssb[ch] + ((ssp[0][1][ch] + ssp[1][1][ch])
                                + (ssp[2][1][ch] + ssp[3][1][ch]));
            ssk[0][ch] = fmaxf(v0, 0.f);
            ssk[1][ch] = fmaxf(v1, 0.f);
        }
        __syncthreads();

        // ---- head m0: h0 = relu(skip @ ow0 + ob0), 16 pre + 48 stream ----
        {
            const float4* W = (const float4*)ow0 + (size_t)kbh * 64 + jqh;
            float4 o0 = {0,0,0,0}, o1 = {0,0,0,0};
            mm_reg<8>(ssk[0] + kbh,      ssk[1] + kbh,      wk, o0, o1);
            mm_reg<8>(ssk[0] + kbh + 8,  ssk[1] + kbh + 8,  ws, o0, o1);
            mm_gl<48>(ssk[0] + kbh + 16, ssk[1] + kbh + 16, W + 16 * 64, 64, o0, o1);
            wload<8>(wk, (const float4*)ow1 + (size_t)kbh * 64 + jqh,       64);
            wload<8>(ws, (const float4*)ow1 + (size_t)(kbh + 8) * 64 + jqh, 64);
            *(float4*)&ssp[ksh][0][4 * jqh] = o0;
            *(float4*)&ssp[ksh][1][4 * jqh] = o1;
        }
        __syncthreads();
        {
            float v0 = obs0[ch] + ((ssp[0][0][ch] + ssp[1][0][ch])
                                 + (ssp[2][0][ch] + ssp[3][0][ch]));
            float v1 = obs0[ch] + ((ssp[0][1][ch] + ssp[1][1][ch])
                                 + (ssp[2][1][ch] + ssp[3][1][ch]));
            sh0[0][ch] = fmaxf(v0, 0.f);
            sh0[1][ch] = fmaxf(v1, 0.f);
        }
        __syncthreads();

        // ---- head m1: logits = h0 @ ow1 + ob1 ----
        {
            const float4* W = (const float4*)ow1 + (size_t)kbh * 64 + jqh;
            float4 o0 = {0,0,0,0}, o1 = {0,0,0,0};
            mm_reg<8>(sh0[0] + kbh,      sh0[1] + kbh,      wk, o0, o1);
            mm_reg<8>(sh0[0] + kbh + 8,  sh0[1] + kbh + 8,  ws, o0, o1);
            mm_gl<48>(sh0[0] + kbh + 16, sh0[1] + kbh + 16, W + 16 * 64, 64, o0, o1);
            // prefetch (t+1, layer 0) conv weights + layer-0 pop
            wload<4>(wk,     (const float4*)kern + (size_t)kbc * 32 + jqc,        32);
            wload<4>(wk + 4, (const float4*)kern + (size_t)(64 + kbc) * 32 + jqc, 32);
            if (tid < 128)
                rpop = g_ring[((size_t)(row0 + r) * RING_PER_ROW) * 64 + c];
            *(float4*)&ssp[ksh][0][4 * jqh] = o0;
            *(float4*)&ssp[ksh][1][4 * jqh] = o1;
        }
        __syncthreads();
        {
            float v0 = obs1[ch] + ((ssp[0][0][ch] + ssp[1][0][ch])
                                 + (ssp[2][0][ch] + ssp[3][0][ch]));
            float v1 = obs1[ch] + ((ssp[0][1][ch] + ssp[1][1][ch])
                                 + (ssp[2][1][ch] + ssp[3][1][ch]));
            slg[0][ch] = v0;
            slg[1][ch] = v1;
            if (mode & 2) {
                out[logit_off + ((size_t)(row0 + 0) * T + t) * VV + ch] = v0;
                out[logit_off + ((size_t)(row0 + 1) * T + t) * VV + ch] = v1;
            }
        }
        __syncthreads();

        // ---- argmax per row (first-max tie rule, matches jnp.argmax) ----
        if (tid < 64) {
            int rr = tid >> 5, lane = tid & 31;
            float bv = -FLT_MAX;
            int bi = 0;
#pragma unroll
            for (int jj = 0; jj < 8; jj++) {
                int j = lane + jj * 32;
                float v = slg[rr][j];
                if (v > bv) { bv = v; bi = j; }
            }
#pragma unroll
            for (int o2 = 16; o2 > 0; o2 >>= 1) {
                float ov = __shfl_down_sync(0xffffffffu, bv, o2);
                int   oi = __shfl_down_sync(0xffffffffu, bi, o2);
                if (ov > bv || (ov == bv && oi < bi)) { bv = ov; bi = oi; }
            }
            if (lane == 0) {
                snidx[rr] = bi;
                if (mode & 1) out[samp_off + (size_t)(row0 + rr) * T + t] = (float)bi;
                if (mode & 4) ((int*)out)[(size_t)(row0 + rr) * T + t] = bi;
            }
        }
        __syncthreads();
    }
}

extern "C" void kernel_launch(void* const* d_in, const int* in_sizes, int n_in,
                              void* d_out, int out_size) {
    const int*   seed  = (const int*)d_in[0];
    const float* emb   = (const float*)d_in[1];
    const float* kern  = (const float*)d_in[2];
    const float* cbias = (const float*)d_in[3];
    const float* rw    = (const float*)d_in[4];
    const float* rb    = (const float*)d_in[5];
    const float* sw    = (const float*)d_in[6];
    const float* sb    = (const float*)d_in[7];
    const float* ow0   = (const float*)d_in[8];
    const float* ob0   = (const float*)d_in[9];
    const float* ow1   = (const float*)d_in[10];
    const float* ob1   = (const float*)d_in[11];
    (void)in_sizes; (void)n_in;

    int T, mode;
    long long samp_off = 0, logit_off = 0;
    if (out_size % (BB * (VV + 1)) == 0) {
        T = out_size / (BB * (VV + 1));
        mode = 1 | 2;                       // float samples then logits
        samp_off = 0;
        logit_off = (long long)BB * T;
    } else if (out_size % (BB * VV) == 0) {
        T = out_size / (BB * VV);
        mode = 2;                           // logits only
        logit_off = 0;
    } else {
        T = out_size / BB;
        mode = 4;                           // int32 samples only
    }

    wavenet_kernel<<<BB / 2, 256>>>(seed, emb, kern, cbias, rw, rb, sw, sb,
                                    ow0, ob0, ow1, ob1,
                                    (float*)d_out, T, samp_off, logit_off, mode);
}